// round 1
// baseline (speedup 1.0000x reference)
#include <cuda_runtime.h>
#include <math.h>

#define D_MODEL 2048
#define D_HID   256
#define N_HEADS 16
#define WINDOW  64
#define MAX_TOK 131072

#define BM 64
#define BK 16
#define XPITCH 65
#define YPITCH 257

// Scratch (device globals: no allocation allowed in kernel_launch)
__device__ float    g_L [(size_t)MAX_TOK * N_HEADS];
__device__ float    g_Vv[(size_t)MAX_TOK * N_HEADS];
__device__ unsigned g_logit_max[N_HEADS];
__device__ unsigned g_score_max[N_HEADS];

// order-preserving float<->uint mapping for atomicMax on floats (handles negatives)
__device__ __forceinline__ unsigned f2ord(float f){
    unsigned u = __float_as_uint(f);
    return (u & 0x80000000u) ? ~u : (u | 0x80000000u);
}
__device__ __forceinline__ float ord2f(unsigned u){
    return (u & 0x80000000u) ? __uint_as_float(u & 0x7fffffffu) : __uint_as_float(~u);
}

__global__ void k_init(){
    int t = threadIdx.x;
    if (t < N_HEADS){
        unsigned ninf = f2ord(-INFINITY);
        g_logit_max[t] = ninf;
        g_score_max[t] = ninf;
    }
}

// Fused: y = relu(x@w1 + b1); L = y@Q^T; V = y@Vv^T  (y never hits HBM)
__global__ __launch_bounds__(256, 2)
void k_mlp(const float* __restrict__ x, const float* __restrict__ w1,
           const float* __restrict__ b1, const float* __restrict__ qw,
           const float* __restrict__ vw, int n)
{
    extern __shared__ float sm[];
    float* ws = sm;              // [BK][256]
    float* xs = sm + BK * 256;   // [BK][XPITCH]
    __shared__ unsigned smax[N_HEADS];

    const int tid = threadIdx.x;
    const int m0  = blockIdx.x * BM;
    const int tm  = tid >> 5;    // 0..7  (row group)
    const int tn  = tid & 31;    // 0..31 (col group)

    if (tid < N_HEADS) smax[tid] = f2ord(-INFINITY);

    float acc[8][8];
    #pragma unroll
    for (int i = 0; i < 8; i++)
        #pragma unroll
        for (int j = 0; j < 8; j++) acc[i][j] = 0.f;

    const int lm = tid >> 2;          // x-load row 0..63
    const int lk = (tid & 3) * 4;     // x-load k offset

    for (int kt = 0; kt < D_MODEL; kt += BK){
        // load x tile [64 x 16] (transposed into xs[k][m])
        float4 xv = *(const float4*)(x + (size_t)(m0 + lm) * D_MODEL + kt + lk);
        xs[(lk + 0) * XPITCH + lm] = xv.x;
        xs[(lk + 1) * XPITCH + lm] = xv.y;
        xs[(lk + 2) * XPITCH + lm] = xv.z;
        xs[(lk + 3) * XPITCH + lm] = xv.w;
        // load w1 tile [16 x 256]
        #pragma unroll
        for (int i = 0; i < 4; i++){
            int qq = tid + 256 * i;
            int r  = qq >> 6;
            int c4 = (qq & 63) * 4;
            *(float4*)(ws + r * 256 + c4) =
                *(const float4*)(w1 + (size_t)(kt + r) * D_HID + c4);
        }
        __syncthreads();
        #pragma unroll
        for (int k = 0; k < BK; k++){
            float a[8], b[8];
            #pragma unroll
            for (int i = 0; i < 8; i++) a[i] = xs[k * XPITCH + tm * 8 + i];
            float4 b0  = *(const float4*)(ws + k * 256 + tn * 4);
            float4 b1v = *(const float4*)(ws + k * 256 + 128 + tn * 4);
            b[0] = b0.x;  b[1] = b0.y;  b[2] = b0.z;  b[3] = b0.w;
            b[4] = b1v.x; b[5] = b1v.y; b[6] = b1v.z; b[7] = b1v.w;
            #pragma unroll
            for (int i = 0; i < 8; i++)
                #pragma unroll
                for (int j = 0; j < 8; j++)
                    acc[i][j] = fmaf(a[i], b[j], acc[i][j]);
        }
        __syncthreads();
    }

    // bias + relu in registers
    #pragma unroll
    for (int j = 0; j < 8; j++){
        int c = (j < 4) ? (tn * 4 + j) : (128 + tn * 4 + (j - 4));
        float bias = b1[c];
        #pragma unroll
        for (int i = 0; i < 8; i++)
            acc[i][j] = fmaxf(acc[i][j] + bias, 0.f);
    }

    // epilogue: stage y rows (two halves of 32 rows to fit 48KB smem),
    // project onto 16 query + 16 value heads
    float* ys = sm;  // [32][YPITCH]
    #pragma unroll 1
    for (int half = 0; half < 2; half++){
        if ((tm >> 2) == half){
            int lrow = (tm & 3) * 8;
            #pragma unroll
            for (int i = 0; i < 8; i++){
                #pragma unroll
                for (int j = 0; j < 8; j++){
                    int c = (j < 4) ? (tn * 4 + j) : (128 + tn * 4 + (j - 4));
                    ys[(lrow + i) * YPITCH + c] = acc[i][j];
                }
            }
        }
        __syncthreads();
        #pragma unroll
        for (int i = 0; i < 4; i++){
            int p = tid + 256 * i;      // 0..1023
            int o = p >> 5;             // 0..31 : same per warp -> broadcast LDG on wrow
            int t = p & 31;             // 0..31 : consecutive -> conflict-free LDS (pitch 257)
            const float* wrow = (o < N_HEADS) ? (qw + o * D_HID)
                                              : (vw + (o - N_HEADS) * D_HID);
            float s = 0.f;
            #pragma unroll 8
            for (int d = 0; d < D_HID; d++)
                s = fmaf(ys[t * YPITCH + d], wrow[d], s);
            int gt = m0 + half * 32 + t;
            if (o < N_HEADS){
                g_L[(size_t)gt * N_HEADS + o] = s;
                atomicMax(&smax[o], f2ord(s));
            } else {
                g_Vv[(size_t)gt * N_HEADS + (o - N_HEADS)] = s;
            }
        }
        __syncthreads();
    }
    if (tid < N_HEADS) atomicMax(&g_logit_max[tid], smax[tid]);
}

// Sliding-window softmax-weighted mean, max over windows per head
__global__ __launch_bounds__(256)
void k_window(int n)
{
    __shared__ float    es [N_HEADS][328];
    __shared__ float    evs[N_HEADS][328];
    __shared__ float    mval[N_HEADS];
    __shared__ unsigned smax[N_HEADS];

    const int tid = threadIdx.x;
    const int w0  = blockIdx.x * 256;
    const int NW  = n - WINDOW + 1;

    if (tid < N_HEADS){
        mval[tid] = ord2f(g_logit_max[tid]);
        smax[tid] = f2ord(-INFINITY);
    }
    __syncthreads();

    int ntok = n - w0;
    if (ntok > 256 + WINDOW - 1) ntok = 256 + WINDOW - 1;   // 319
    for (int idx = tid; idx < ntok * N_HEADS; idx += 256){
        int h = idx & (N_HEADS - 1);
        int t = idx >> 4;
        size_t g = (size_t)(w0 + t) * N_HEADS + h;
        float e = expf(g_L[g] - mval[h]);
        es [h][t] = e;
        evs[h][t] = e * g_Vv[g];
    }
    __syncthreads();

    if (w0 + tid < NW){
        #pragma unroll 1
        for (int h = 0; h < N_HEADS; h++){
            float se = 0.f, sev = 0.f;
            #pragma unroll 16
            for (int j = 0; j < WINDOW; j++){
                se  += es [h][tid + j];
                sev += evs[h][tid + j];
            }
            atomicMax(&smax[h], f2ord(sev / se));
        }
    }
    __syncthreads();
    if (tid < N_HEADS) atomicMax(&g_score_max[tid], smax[tid]);
}

__global__ void k_final(float* out){
    int t = threadIdx.x;
    float s = (t < N_HEADS) ? ord2f(g_score_max[t]) : 0.f;
    #pragma unroll
    for (int off = 16; off; off >>= 1)
        s += __shfl_down_sync(0xffffffffu, s, off);
    if (t == 0) out[0] = s;
}

extern "C" void kernel_launch(void* const* d_in, const int* in_sizes, int n_in,
                              void* d_out, int out_size)
{
    const float* x  = (const float*)d_in[0];
    const float* w1 = (const float*)d_in[1];
    const float* b1 = (const float*)d_in[2];
    const float* qw = (const float*)d_in[3];
    const float* vw = (const float*)d_in[4];
    int n = in_sizes[0] / D_MODEL;

    // dynamic smem: max(phase1: 16*256 + 16*65, epilogue: 32*257) floats = 32896 B
    size_t ph1  = (size_t)(BK * 256 + BK * XPITCH);
    size_t ph2  = (size_t)(32 * YPITCH);
    size_t smem = sizeof(float) * (ph1 > ph2 ? ph1 : ph2);

    k_init<<<1, 32>>>();
    k_mlp<<<n / BM, 256, smem>>>(x, w1, b1, qw, vw, n);
    int NW = n - WINDOW + 1;
    k_window<<<(NW + 255) / 256, 256>>>(n);
    k_final<<<1, 32>>>((float*)d_out);
}

// round 3
// speedup vs baseline: 3.1286x; 3.1286x over previous
#include <cuda_runtime.h>
#include <cuda_fp16.h>
#include <math.h>
#include <stdint.h>

#define D_MODEL 2048
#define D_HID   256
#define N_HEADS 16
#define WINDOW  64
#define MAX_TOK 131072

// ---------------- device scratch (no allocs allowed) ----------------
__device__ float    g_L [(size_t)MAX_TOK * N_HEADS];
__device__ float    g_Vv[(size_t)MAX_TOK * N_HEADS];
__device__ __half   g_w1h[(size_t)D_HID * D_MODEL];   // w1 transposed+fp16 [256][2048]
__device__ unsigned g_logit_max[N_HEADS];
__device__ unsigned g_score_max[N_HEADS];

// ---------------- helpers ----------------
__device__ __forceinline__ unsigned f2ord(float f){
    unsigned u = __float_as_uint(f);
    return (u & 0x80000000u) ? ~u : (u | 0x80000000u);
}
__device__ __forceinline__ float ord2f(unsigned u){
    return (u & 0x80000000u) ? __uint_as_float(u & 0x7fffffffu) : __uint_as_float(~u);
}
__device__ __forceinline__ uint32_t smem_u32(const void* p){
    uint32_t a;
    asm("{ .reg .u64 t; cvta.to.shared.u64 t, %1; cvt.u32.u64 %0, t; }" : "=r"(a) : "l"(p));
    return a;
}
__device__ __forceinline__ uint32_t pack_h2(float lo, float hi){
    __half2 h = __floats2half2_rn(lo, hi);   // lo -> low half
    return *reinterpret_cast<uint32_t*>(&h);
}
__device__ __forceinline__ void mma16816(float* c, const uint32_t* a, const uint32_t* b){
    asm volatile(
        "mma.sync.aligned.m16n8k16.row.col.f32.f16.f16.f32 "
        "{%0,%1,%2,%3}, {%4,%5,%6,%7}, {%8,%9}, {%0,%1,%2,%3};"
        : "+f"(c[0]), "+f"(c[1]), "+f"(c[2]), "+f"(c[3])
        : "r"(a[0]), "r"(a[1]), "r"(a[2]), "r"(a[3]), "r"(b[0]), "r"(b[1]));
}

// ---------------- kernels ----------------
__global__ void k_init(){
    int t = threadIdx.x;
    if (t < N_HEADS){
        unsigned ninf = ~0xFF800000u;  // f2ord(-inf)
        g_logit_max[t] = ninf;
        g_score_max[t] = ninf;
    }
}

// w1 [2048][256] fp32 -> g_w1h [256][2048] fp16
__global__ void k_prep_w(const float* __restrict__ w1){
    __shared__ float t[32][33];
    int k0 = blockIdx.x * 32, n0 = blockIdx.y * 32;
    int tx = threadIdx.x, ty = threadIdx.y;     // 32 x 8
    #pragma unroll
    for (int i = ty; i < 32; i += 8)
        t[i][tx] = w1[(size_t)(k0 + i) * D_HID + n0 + tx];
    __syncthreads();
    #pragma unroll
    for (int i = ty; i < 32; i += 8)
        g_w1h[(size_t)(n0 + i) * D_MODEL + k0 + tx] = __float2half_rn(t[tx][i]);
}

// ---------------- fused MLP + head projection (HMMA) ----------------
#define BK        32
#define KT_TILES  (D_MODEL / BK)      // 64
#define A_STRIDE  40                   // fp32 words per A smem row (bank-tuned)
#define B_STRIDE  80                   // bytes per B smem row (bank-tuned)
#define A_BYTES   (128 * A_STRIDE * 4) // 20480
#define B_BYTES   (256 * B_STRIDE)     // 20480
#define STAGE_BYTES (A_BYTES + B_BYTES)
#define SMEM_DYN  (3 * STAGE_BYTES)    // 122880

__device__ __forceinline__ void load_stage(const float* __restrict__ x, size_t m0,
                                           int kt, uint32_t sA, uint32_t sB, int tid){
    #pragma unroll
    for (int i = 0; i < 2; i++){
        int ch  = tid + i * 512;            // 0..1023
        int row = ch >> 3, c = ch & 7;      // A: 128 rows x 8 chunks
        const float* src = x + (m0 + row) * D_MODEL + (size_t)kt * BK + c * 4;
        uint32_t dst = sA + row * (A_STRIDE * 4) + c * 16;
        asm volatile("cp.async.cg.shared.global [%0], [%1], 16;" :: "r"(dst), "l"(src));
    }
    #pragma unroll
    for (int i = 0; i < 2; i++){
        int ch  = tid + i * 512;
        int row = ch >> 2, c = ch & 3;      // B: 256 rows x 4 chunks
        const char* src = (const char*)g_w1h + (size_t)row * (D_MODEL * 2) + kt * (BK * 2) + c * 16;
        uint32_t dst = sB + row * B_STRIDE + c * 16;
        asm volatile("cp.async.cg.shared.global [%0], [%1], 16;" :: "r"(dst), "l"(src));
    }
}

__global__ __launch_bounds__(512, 1)
void k_mlp(const float* __restrict__ x, const float* __restrict__ b1,
           const float* __restrict__ qw, const float* __restrict__ vw)
{
    extern __shared__ __align__(16) char dyn[];
    __shared__ unsigned smax[N_HEADS];

    const int tid  = threadIdx.x;
    const int wid  = tid >> 5;
    const int lane = tid & 31;
    const int mw   = wid >> 2;      // 0..3  M warp
    const int nw   = wid & 3;       // 0..3  N warp
    const int rq   = lane >> 2;     // 0..7
    const int cq   = (lane & 3) * 2;
    const size_t m0 = (size_t)blockIdx.x * 128;

    const uint32_t dbase = smem_u32(dyn);
    if (tid < N_HEADS) smax[tid] = ~0xFF800000u;

    float acc[2][8][4];
    #pragma unroll
    for (int mt = 0; mt < 2; mt++)
        #pragma unroll
        for (int nt = 0; nt < 8; nt++)
            #pragma unroll
            for (int k = 0; k < 4; k++) acc[mt][nt][k] = 0.f;

    // prologue
    load_stage(x, m0, 0, dbase, dbase + A_BYTES, tid);
    asm volatile("cp.async.commit_group;" ::: "memory");
    load_stage(x, m0, 1, dbase + STAGE_BYTES, dbase + STAGE_BYTES + A_BYTES, tid);
    asm volatile("cp.async.commit_group;" ::: "memory");

    for (int kt = 0; kt < KT_TILES; kt++){
        asm volatile("cp.async.wait_group 1;" ::: "memory");
        __syncthreads();

        const uint32_t st = dbase + (kt % 3) * STAGE_BYTES;
        const float* As = (const float*)(dyn + (kt % 3) * STAGE_BYTES);
        const uint32_t sB = st + A_BYTES;

        #pragma unroll
        for (int ks = 0; ks < 2; ks++){
            const int kk = ks * 16 + cq;
            // B fragments: 8 n-tiles (no .trans: [N][K] storage, consecutive-k regs)
            uint32_t bf[8][2];
            #pragma unroll
            for (int ng = 0; ng < 4; ng++){
                int m = lane >> 3, r = lane & 7;
                int nrow = nw * 64 + ng * 16 + ((m >> 1) * 8) + r;
                uint32_t addr = sB + nrow * B_STRIDE + (ks * 16 + (m & 1) * 8) * 2;
                asm volatile(
                    "ldmatrix.sync.aligned.m8n8.x4.shared.b16 {%0,%1,%2,%3}, [%4];"
                    : "=r"(bf[ng*2][0]), "=r"(bf[ng*2][1]),
                      "=r"(bf[ng*2+1][0]), "=r"(bf[ng*2+1][1])
                    : "r"(addr));
            }
            #pragma unroll
            for (int mt = 0; mt < 2; mt++){
                const int R = mw * 32 + mt * 16 + rq;
                float2 q00 = *(const float2*)&As[(size_t)R * A_STRIDE + kk];
                float2 q10 = *(const float2*)&As[(size_t)(R + 8) * A_STRIDE + kk];
                float2 q01 = *(const float2*)&As[(size_t)R * A_STRIDE + kk + 8];
                float2 q11 = *(const float2*)&As[(size_t)(R + 8) * A_STRIDE + kk + 8];
                uint32_t ah[4] = { pack_h2(q00.x, q00.y), pack_h2(q10.x, q10.y),
                                   pack_h2(q01.x, q01.y), pack_h2(q11.x, q11.y) };
                #pragma unroll
                for (int nt = 0; nt < 8; nt++) mma16816(acc[mt][nt], ah, bf[nt]);
                // residual (lo) term
                float2 h0 = __half22float2(*(__half2*)&ah[0]);
                float2 h1 = __half22float2(*(__half2*)&ah[1]);
                float2 h2 = __half22float2(*(__half2*)&ah[2]);
                float2 h3 = __half22float2(*(__half2*)&ah[3]);
                uint32_t al[4] = { pack_h2(q00.x - h0.x, q00.y - h0.y),
                                   pack_h2(q10.x - h1.x, q10.y - h1.y),
                                   pack_h2(q01.x - h2.x, q01.y - h2.y),
                                   pack_h2(q11.x - h3.x, q11.y - h3.y) };
                #pragma unroll
                for (int nt = 0; nt < 8; nt++) mma16816(acc[mt][nt], al, bf[nt]);
            }
        }
        __syncthreads();
        if (kt + 2 < KT_TILES){
            uint32_t ns = dbase + ((kt + 2) % 3) * STAGE_BYTES;
            load_stage(x, m0, kt + 2, ns, ns + A_BYTES, tid);
        }
        asm volatile("cp.async.commit_group;" ::: "memory");
    }
    asm volatile("cp.async.wait_group 0;" ::: "memory");
    __syncthreads();

    // ---------------- epilogue ----------------
    float* smf = (float*)dyn;      // [0,8192): qw|vw  [8192,8448): bias  [8448,+8224): ys
    for (int i = tid; i < 4096; i += 512) smf[i]        = qw[i];
    for (int i = tid; i < 4096; i += 512) smf[4096 + i] = vw[i];
    if (tid < 256) smf[8192 + tid] = b1[tid];
    __syncthreads();

    // bias + relu in regs
    #pragma unroll
    for (int mt = 0; mt < 2; mt++)
        #pragma unroll
        for (int nt = 0; nt < 8; nt++){
            int C = nw * 64 + nt * 8 + cq;
            float bv0 = smf[8192 + C], bv1 = smf[8192 + C + 1];
            acc[mt][nt][0] = fmaxf(acc[mt][nt][0] + bv0, 0.f);
            acc[mt][nt][1] = fmaxf(acc[mt][nt][1] + bv1, 0.f);
            acc[mt][nt][2] = fmaxf(acc[mt][nt][2] + bv0, 0.f);
            acc[mt][nt][3] = fmaxf(acc[mt][nt][3] + bv1, 0.f);
        }

    float* ys = smf + 8448;        // [32][257]
    #pragma unroll 1
    for (int p = 0; p < 4; p++){
        if (mw == p){
            #pragma unroll
            for (int mt = 0; mt < 2; mt++)
                #pragma unroll
                for (int nt = 0; nt < 8; nt++){
                    int lr = mt * 16 + rq;
                    int C  = nw * 64 + nt * 8 + cq;
                    ys[lr * 257 + C]           = acc[mt][nt][0];
                    ys[lr * 257 + C + 1]       = acc[mt][nt][1];
                    ys[(lr + 8) * 257 + C]     = acc[mt][nt][2];
                    ys[(lr + 8) * 257 + C + 1] = acc[mt][nt][3];
                }
        }
        __syncthreads();
        #pragma unroll
        for (int i = 0; i < 2; i++){
            int pidx = tid + 512 * i;        // 0..1023
            int o = pidx >> 5;               // 0..31 (same per warp -> broadcast)
            int t = pidx & 31;
            const float* wrow = smf + o * 256;
            float s = 0.f;
            #pragma unroll 8
            for (int d = 0; d < 256; d++)
                s = fmaf(ys[t * 257 + d], wrow[d], s);
            size_t gt = m0 + p * 32 + t;
            if (o < N_HEADS){
                g_L[gt * N_HEADS + o] = s;
                atomicMax(&smax[o], f2ord(s));
            } else {
                g_Vv[gt * N_HEADS + (o - N_HEADS)] = s;
            }
        }
        __syncthreads();
    }
    if (tid < N_HEADS) atomicMax(&g_logit_max[tid], smax[tid]);
}

// Sliding-window softmax-weighted mean, max over windows per head
__global__ __launch_bounds__(256)
void k_window(int n)
{
    __shared__ float    es [N_HEADS][328];
    __shared__ float    evs[N_HEADS][328];
    __shared__ float    mval[N_HEADS];
    __shared__ unsigned smax[N_HEADS];

    const int tid = threadIdx.x;
    const int w0  = blockIdx.x * 256;
    const int NW  = n - WINDOW + 1;

    if (tid < N_HEADS){
        mval[tid] = ord2f(g_logit_max[tid]);
        smax[tid] = f2ord(-INFINITY);
    }
    __syncthreads();

    int ntok = n - w0;
    if (ntok > 256 + WINDOW - 1) ntok = 256 + WINDOW - 1;
    for (int idx = tid; idx < ntok * N_HEADS; idx += 256){
        int h = idx & (N_HEADS - 1);
        int t = idx >> 4;
        size_t g = (size_t)(w0 + t) * N_HEADS + h;
        float e = expf(g_L[g] - mval[h]);
        es [h][t] = e;
        evs[h][t] = e * g_Vv[g];
    }
    __syncthreads();

    if (w0 + tid < NW){
        #pragma unroll 1
        for (int h = 0; h < N_HEADS; h++){
            float se = 0.f, sev = 0.f;
            #pragma unroll 16
            for (int j = 0; j < WINDOW; j++){
                se  += es [h][tid + j];
                sev += evs[h][tid + j];
            }
            atomicMax(&smax[h], f2ord(sev / se));
        }
    }
    __syncthreads();
    if (tid < N_HEADS) atomicMax(&g_score_max[tid], smax[tid]);
}

__global__ void k_final(float* out){
    int t = threadIdx.x;
    float s = (t < N_HEADS) ? ord2f(g_score_max[t]) : 0.f;
    #pragma unroll
    for (int off = 16; off; off >>= 1)
        s += __shfl_down_sync(0xffffffffu, s, off);
    if (t == 0) out[0] = s;
}

extern "C" void kernel_launch(void* const* d_in, const int* in_sizes, int n_in,
                              void* d_out, int out_size)
{
    const float* x  = (const float*)d_in[0];
    const float* w1 = (const float*)d_in[1];
    const float* b1 = (const float*)d_in[2];
    const float* qw = (const float*)d_in[3];
    const float* vw = (const float*)d_in[4];
    int n = in_sizes[0] / D_MODEL;

    cudaFuncSetAttribute(k_mlp, cudaFuncAttributeMaxDynamicSharedMemorySize, SMEM_DYN);

    k_init<<<1, 32>>>();
    k_prep_w<<<dim3(D_MODEL / 32, D_HID / 32), dim3(32, 8)>>>(w1);
    k_mlp<<<n / 128, 512, SMEM_DYN>>>(x, b1, qw, vw);
    int NW = n - WINDOW + 1;
    k_window<<<(NW + 255) / 256, 256>>>(n);
    k_final<<<1, 32>>>((float*)d_out);
}

// round 4
// speedup vs baseline: 5.6450x; 1.8043x over previous
#include <cuda_runtime.h>
#include <cuda_fp16.h>
#include <math.h>
#include <stdint.h>

#define D_MODEL 2048
#define D_HID   256
#define N_HEADS 16
#define WINDOW  64
#define MAX_TOK 131072

// ---------------- device scratch (no allocs allowed) ----------------
__device__ float    g_L [(size_t)MAX_TOK * N_HEADS];
__device__ float    g_Vv[(size_t)MAX_TOK * N_HEADS];
__device__ __half   g_w1h[(size_t)D_HID * D_MODEL];   // w1 transposed+fp16 [256][2048]
__device__ __half   g_qvh[32 * D_HID];                // [16 q heads | 16 v heads][256] fp16
__device__ unsigned g_logit_max[N_HEADS];
__device__ unsigned g_score_max[N_HEADS];

// ---------------- helpers ----------------
__device__ __forceinline__ unsigned f2ord(float f){
    unsigned u = __float_as_uint(f);
    return (u & 0x80000000u) ? ~u : (u | 0x80000000u);
}
__device__ __forceinline__ float ord2f(unsigned u){
    return (u & 0x80000000u) ? __uint_as_float(u & 0x7fffffffu) : __uint_as_float(~u);
}
__device__ __forceinline__ uint32_t smem_u32(const void* p){
    uint32_t a;
    asm("{ .reg .u64 t; cvta.to.shared.u64 t, %1; cvt.u32.u64 %0, t; }" : "=r"(a) : "l"(p));
    return a;
}
__device__ __forceinline__ uint32_t pack_h2(float lo, float hi){
    __half2 h = __floats2half2_rn(lo, hi);   // lo -> low half
    return *reinterpret_cast<uint32_t*>(&h);
}
__device__ __forceinline__ void mma16816(float* c, const uint32_t* a, const uint32_t* b){
    asm volatile(
        "mma.sync.aligned.m16n8k16.row.col.f32.f16.f16.f32 "
        "{%0,%1,%2,%3}, {%4,%5,%6,%7}, {%8,%9}, {%0,%1,%2,%3};"
        : "+f"(c[0]), "+f"(c[1]), "+f"(c[2]), "+f"(c[3])
        : "r"(a[0]), "r"(a[1]), "r"(a[2]), "r"(a[3]), "r"(b[0]), "r"(b[1]));
}
#define LDMX4(r0, r1, r2, r3, addr) \
    asm volatile("ldmatrix.sync.aligned.m8n8.x4.shared.b16 {%0,%1,%2,%3}, [%4];" \
                 : "=r"(r0), "=r"(r1), "=r"(r2), "=r"(r3) : "r"(addr))

// ---------------- kernels ----------------
__global__ void k_init(){
    int t = threadIdx.x;
    if (t < N_HEADS){
        unsigned ninf = ~0xFF800000u;  // f2ord(-inf)
        g_logit_max[t] = ninf;
        g_score_max[t] = ninf;
    }
}

// w1 [2048][256] fp32 -> g_w1h [256][2048] fp16
__global__ void k_prep_w(const float* __restrict__ w1){
    __shared__ float t[32][33];
    int k0 = blockIdx.x * 32, n0 = blockIdx.y * 32;
    int tx = threadIdx.x, ty = threadIdx.y;     // 32 x 8
    #pragma unroll
    for (int i = ty; i < 32; i += 8)
        t[i][tx] = w1[(size_t)(k0 + i) * D_HID + n0 + tx];
    __syncthreads();
    #pragma unroll
    for (int i = ty; i < 32; i += 8)
        g_w1h[(size_t)(n0 + i) * D_MODEL + k0 + tx] = __float2half_rn(t[tx][i]);
}

// qw,vw [16][256] fp32 -> g_qvh [32][256] fp16
__global__ void k_prep_qv(const float* __restrict__ qw, const float* __restrict__ vw){
    int i = blockIdx.x * 256 + threadIdx.x;
    if (i < 4096)      g_qvh[i]        = __float2half_rn(qw[i]);
    else if (i < 8192) g_qvh[i]        = __float2half_rn(vw[i - 4096]);
}

// ---------------- fused MLP + head projection (HMMA) ----------------
#define BK        32
#define KT_TILES  (D_MODEL / BK)       // 64
#define A_STRIDE  40                   // fp32 words per A smem row (bank-tuned)
#define B_STRIDE  80                   // bytes per B smem row (bank-tuned)
#define A_BYTES   (128 * A_STRIDE * 4) // 20480
#define B_BYTES   (256 * B_STRIDE)     // 20480
#define STAGE_BYTES (A_BYTES + B_BYTES)
#define N_STAGES  4
#define SMEM_DYN  (N_STAGES * STAGE_BYTES)   // 163840

__device__ __forceinline__ void load_stage(const float* __restrict__ x, size_t m0,
                                           int kt, uint32_t sA, uint32_t sB, int tid){
    #pragma unroll
    for (int i = 0; i < 2; i++){
        int ch  = tid + i * 512;            // 0..1023
        int row = ch >> 3, c = ch & 7;      // A: 128 rows x 8 chunks of 16B
        const float* src = x + (m0 + row) * D_MODEL + (size_t)kt * BK + c * 4;
        uint32_t dst = sA + row * (A_STRIDE * 4) + c * 16;
        asm volatile("cp.async.cg.shared.global [%0], [%1], 16;" :: "r"(dst), "l"(src));
    }
    #pragma unroll
    for (int i = 0; i < 2; i++){
        int ch  = tid + i * 512;
        int row = ch >> 2, c = ch & 3;      // B: 256 rows x 4 chunks of 16B
        const char* src = (const char*)g_w1h + (size_t)row * (D_MODEL * 2) + kt * (BK * 2) + c * 16;
        uint32_t dst = sB + row * B_STRIDE + c * 16;
        asm volatile("cp.async.cg.shared.global [%0], [%1], 16;" :: "r"(dst), "l"(src));
    }
}

__global__ __launch_bounds__(512, 1)
void k_mlp(const float* __restrict__ x, const float* __restrict__ b1)
{
    extern __shared__ __align__(16) char dyn[];
    __shared__ unsigned smax[N_HEADS];

    const int tid  = threadIdx.x;
    const int wid  = tid >> 5;
    const int lane = tid & 31;
    const int mw   = wid >> 2;      // 0..3  M warp
    const int nw   = wid & 3;       // 0..3  N warp
    const int rq   = lane >> 2;     // 0..7
    const int cq   = (lane & 3) * 2;
    const size_t m0 = (size_t)blockIdx.x * 128;

    const uint32_t dbase = smem_u32(dyn);
    if (tid < N_HEADS) smax[tid] = ~0xFF800000u;

    float acc[2][8][4];
    #pragma unroll
    for (int mt = 0; mt < 2; mt++)
        #pragma unroll
        for (int nt = 0; nt < 8; nt++)
            #pragma unroll
            for (int k = 0; k < 4; k++) acc[mt][nt][k] = 0.f;

    // prologue: 3 stages in flight
    #pragma unroll
    for (int p = 0; p < 3; p++){
        uint32_t st = dbase + p * STAGE_BYTES;
        load_stage(x, m0, p, st, st + A_BYTES, tid);
        asm volatile("cp.async.commit_group;" ::: "memory");
    }

    for (int kt = 0; kt < KT_TILES; kt++){
        asm volatile("cp.async.wait_group 2;" ::: "memory");
        __syncthreads();

        if (kt + 3 < KT_TILES){
            uint32_t ns = dbase + ((kt + 3) % N_STAGES) * STAGE_BYTES;
            load_stage(x, m0, kt + 3, ns, ns + A_BYTES, tid);
        }
        asm volatile("cp.async.commit_group;" ::: "memory");

        const int s = kt % N_STAGES;
        const float* As = (const float*)(dyn + s * STAGE_BYTES);
        const uint32_t sB = dbase + s * STAGE_BYTES + A_BYTES;

        #pragma unroll
        for (int ks = 0; ks < 2; ks++){
            const int kk = ks * 16 + cq;
            uint32_t bf[8][2];
            #pragma unroll
            for (int ng = 0; ng < 4; ng++){
                int m = lane >> 3, r = lane & 7;
                int nrow = nw * 64 + ng * 16 + ((m >> 1) * 8) + r;
                uint32_t addr = sB + nrow * B_STRIDE + (ks * 16 + (m & 1) * 8) * 2;
                LDMX4(bf[ng*2][0], bf[ng*2][1], bf[ng*2+1][0], bf[ng*2+1][1], addr);
            }
            #pragma unroll
            for (int mt = 0; mt < 2; mt++){
                const int R = mw * 32 + mt * 16 + rq;
                float2 q00 = *(const float2*)&As[(size_t)R * A_STRIDE + kk];
                float2 q10 = *(const float2*)&As[(size_t)(R + 8) * A_STRIDE + kk];
                float2 q01 = *(const float2*)&As[(size_t)R * A_STRIDE + kk + 8];
                float2 q11 = *(const float2*)&As[(size_t)(R + 8) * A_STRIDE + kk + 8];
                uint32_t ah[4] = { pack_h2(q00.x, q00.y), pack_h2(q10.x, q10.y),
                                   pack_h2(q01.x, q01.y), pack_h2(q11.x, q11.y) };
                #pragma unroll
                for (int nt = 0; nt < 8; nt++) mma16816(acc[mt][nt], ah, bf[nt]);
            }
        }
    }
    __syncthreads();   // mainloop smem reads done; reuse dyn below

    // ---------------- epilogue: bias + relu, then projection MMA ----------------
    // bias + relu on accumulators
    #pragma unroll
    for (int nt = 0; nt < 8; nt++){
        int C = nw * 64 + nt * 8 + cq;
        float bv0 = __ldg(b1 + C), bv1 = __ldg(b1 + C + 1);
        #pragma unroll
        for (int mt = 0; mt < 2; mt++){
            acc[mt][nt][0] = fmaxf(acc[mt][nt][0] + bv0, 0.f);
            acc[mt][nt][1] = fmaxf(acc[mt][nt][1] + bv1, 0.f);
            acc[mt][nt][2] = fmaxf(acc[mt][nt][2] + bv0, 0.f);
            acc[mt][nt][3] = fmaxf(acc[mt][nt][3] + bv1, 0.f);
        }
    }

    float*  proj = (float*)dyn;                 // [128][33] fp32
    __half* qvs  = (__half*)(dyn + 17408);      // [32 rows][264 halves] (528B stride)
    for (int i = tid; i < 128 * 33; i += 512) proj[i] = 0.f;
    for (int i = tid; i < 32 * 256; i += 512){
        int r = i >> 8, c = i & 255;
        qvs[r * 264 + c] = g_qvh[i];
    }
    __syncthreads();

    const uint32_t qbase = smem_u32(qvs);
    // projection: LV[128 tok][32 heads] = y[128][256] @ qv^T, per-warp partial over 64 hid dims
    #pragma unroll
    for (int mt = 0; mt < 2; mt++){
        float cp[4][4];
        #pragma unroll
        for (int ht = 0; ht < 4; ht++)
            #pragma unroll
            for (int k = 0; k < 4; k++) cp[ht][k] = 0.f;
        #pragma unroll
        for (int j = 0; j < 4; j++){    // k16 chunks within this warp's 64 hid dims
            uint32_t bh[4][2];
            #pragma unroll
            for (int hg = 0; hg < 2; hg++){
                int m = lane >> 3, r = lane & 7;
                int hrow = hg * 16 + ((m >> 1) * 8) + r;
                uint32_t addr = qbase + hrow * 528 + (nw * 64 + j * 16 + (m & 1) * 8) * 2;
                LDMX4(bh[hg*2][0], bh[hg*2][1], bh[hg*2+1][0], bh[hg*2+1][1], addr);
            }
            // C-frag pair (nt=2j, 2j+1) == A-frag m16k16 layout
            uint32_t ap[4] = {
                pack_h2(acc[mt][2*j  ][0], acc[mt][2*j  ][1]),
                pack_h2(acc[mt][2*j  ][2], acc[mt][2*j  ][3]),
                pack_h2(acc[mt][2*j+1][0], acc[mt][2*j+1][1]),
                pack_h2(acc[mt][2*j+1][2], acc[mt][2*j+1][3]) };
            #pragma unroll
            for (int ht = 0; ht < 4; ht++) mma16816(cp[ht], ap, bh[ht]);
        }
        int tok = mw * 32 + mt * 16 + rq;
        #pragma unroll
        for (int ht = 0; ht < 4; ht++){
            int hd = ht * 8 + cq;
            atomicAdd(&proj[tok * 33 + hd],           cp[ht][0]);
            atomicAdd(&proj[tok * 33 + hd + 1],       cp[ht][1]);
            atomicAdd(&proj[(tok + 8) * 33 + hd],     cp[ht][2]);
            atomicAdd(&proj[(tok + 8) * 33 + hd + 1], cp[ht][3]);
        }
    }
    __syncthreads();

    // write out L, V and per-head logit max
    #pragma unroll
    for (int i = 0; i < 8; i++){
        int idx = tid + 512 * i;       // 0..4095
        int t = idx >> 5, h = idx & 31;
        float s = proj[t * 33 + h];
        size_t gt = m0 + t;
        if (h < N_HEADS){
            g_L[gt * N_HEADS + h] = s;
            atomicMax(&smax[h], f2ord(s));
        } else {
            g_Vv[gt * N_HEADS + (h - N_HEADS)] = s;
        }
    }
    __syncthreads();
    if (tid < N_HEADS) atomicMax(&g_logit_max[tid], smax[tid]);
}

// Sliding-window softmax-weighted mean, max over windows per head
__global__ __launch_bounds__(256)
void k_window(int n)
{
    __shared__ float    es [N_HEADS][328];
    __shared__ float    evs[N_HEADS][328];
    __shared__ float    mval[N_HEADS];
    __shared__ unsigned smax[N_HEADS];

    const int tid = threadIdx.x;
    const int w0  = blockIdx.x * 256;
    const int NW  = n - WINDOW + 1;

    if (tid < N_HEADS){
        mval[tid] = ord2f(g_logit_max[tid]);
        smax[tid] = f2ord(-INFINITY);
    }
    __syncthreads();

    int ntok = n - w0;
    if (ntok > 256 + WINDOW - 1) ntok = 256 + WINDOW - 1;
    for (int idx = tid; idx < ntok * N_HEADS; idx += 256){
        int h = idx & (N_HEADS - 1);
        int t = idx >> 4;
        size_t g = (size_t)(w0 + t) * N_HEADS + h;
        float e = expf(g_L[g] - mval[h]);
        es [h][t] = e;
        evs[h][t] = e * g_Vv[g];
    }
    __syncthreads();

    if (w0 + tid < NW){
        #pragma unroll 1
        for (int h = 0; h < N_HEADS; h++){
            float se = 0.f, sev = 0.f;
            #pragma unroll 16
            for (int j = 0; j < WINDOW; j++){
                se  += es [h][tid + j];
                sev += evs[h][tid + j];
            }
            atomicMax(&smax[h], f2ord(sev / se));
        }
    }
    __syncthreads();
    if (tid < N_HEADS) atomicMax(&g_score_max[tid], smax[tid]);
}

__global__ void k_final(float* out){
    int t = threadIdx.x;
    float s = (t < N_HEADS) ? ord2f(g_score_max[t]) : 0.f;
    #pragma unroll
    for (int off = 16; off; off >>= 1)
        s += __shfl_down_sync(0xffffffffu, s, off);
    if (t == 0) out[0] = s;
}

extern "C" void kernel_launch(void* const* d_in, const int* in_sizes, int n_in,
                              void* d_out, int out_size)
{
    const float* x  = (const float*)d_in[0];
    const float* w1 = (const float*)d_in[1];
    const float* b1 = (const float*)d_in[2];
    const float* qw = (const float*)d_in[3];
    const float* vw = (const float*)d_in[4];
    int n = in_sizes[0] / D_MODEL;

    cudaFuncSetAttribute(k_mlp, cudaFuncAttributeMaxDynamicSharedMemorySize, SMEM_DYN);

    k_init<<<1, 32>>>();
    k_prep_w<<<dim3(D_MODEL / 32, D_HID / 32), dim3(32, 8)>>>(w1);
    k_prep_qv<<<32, 256>>>(qw, vw);
    k_mlp<<<n / 128, 512, SMEM_DYN>>>(x, b1);
    int NW = n - WINDOW + 1;
    k_window<<<(NW + 255) / 256, 256>>>(n);
    k_final<<<1, 32>>>((float*)d_out);
}

// round 5
// speedup vs baseline: 6.0367x; 1.0694x over previous
#include <cuda_runtime.h>
#include <cuda_fp16.h>
#include <math.h>
#include <stdint.h>

#define D_MODEL 2048
#define D_HID   256
#define N_HEADS 16
#define WINDOW  64
#define MAX_TOK 131072

// ---------------- device scratch (no allocs allowed) ----------------
__device__ float    g_L [(size_t)MAX_TOK * N_HEADS];
__device__ float    g_Vv[(size_t)MAX_TOK * N_HEADS];
__device__ __half   g_w1h[(size_t)D_HID * D_MODEL];   // w1 transposed+fp16 [256][2048]
__device__ __half   g_qvh[32 * D_HID];                // [16 q | 16 v heads][256] fp16
__device__ unsigned g_logit_max[N_HEADS];
__device__ unsigned g_score_max[N_HEADS];

// ---------------- helpers ----------------
__device__ __forceinline__ unsigned f2ord(float f){
    unsigned u = __float_as_uint(f);
    return (u & 0x80000000u) ? ~u : (u | 0x80000000u);
}
__device__ __forceinline__ float ord2f(unsigned u){
    return (u & 0x80000000u) ? __uint_as_float(u & 0x7fffffffu) : __uint_as_float(~u);
}
__device__ __forceinline__ uint32_t smem_u32(const void* p){
    uint32_t a;
    asm("{ .reg .u64 t; cvta.to.shared.u64 t, %1; cvt.u32.u64 %0, t; }" : "=r"(a) : "l"(p));
    return a;
}
__device__ __forceinline__ uint32_t pack_h2(float lo, float hi){
    __half2 h = __floats2half2_rn(lo, hi);
    return *reinterpret_cast<uint32_t*>(&h);
}
__device__ __forceinline__ void mma16816(float* c, const uint32_t* a, const uint32_t* b){
    asm volatile(
        "mma.sync.aligned.m16n8k16.row.col.f32.f16.f16.f32 "
        "{%0,%1,%2,%3}, {%4,%5,%6,%7}, {%8,%9}, {%0,%1,%2,%3};"
        : "+f"(c[0]), "+f"(c[1]), "+f"(c[2]), "+f"(c[3])
        : "r"(a[0]), "r"(a[1]), "r"(a[2]), "r"(a[3]), "r"(b[0]), "r"(b[1]));
}
#define LDMX4(r0, r1, r2, r3, addr) \
    asm volatile("ldmatrix.sync.aligned.m8n8.x4.shared.b16 {%0,%1,%2,%3}, [%4];" \
                 : "=r"(r0), "=r"(r1), "=r"(r2), "=r"(r3) : "r"(addr))

// ---------------- kernels ----------------
__global__ void k_init(){
    int t = threadIdx.x;
    if (t < N_HEADS){
        unsigned ninf = ~0xFF800000u;  // f2ord(-inf)
        g_logit_max[t] = ninf;
        g_score_max[t] = ninf;
    }
}

// w1 [2048][256] fp32 -> g_w1h [256][2048] fp16
__global__ void k_prep_w(const float* __restrict__ w1){
    __shared__ float t[32][33];
    int k0 = blockIdx.x * 32, n0 = blockIdx.y * 32;
    int tx = threadIdx.x, ty = threadIdx.y;     // 32 x 8
    #pragma unroll
    for (int i = ty; i < 32; i += 8)
        t[i][tx] = w1[(size_t)(k0 + i) * D_HID + n0 + tx];
    __syncthreads();
    #pragma unroll
    for (int i = ty; i < 32; i += 8)
        g_w1h[(size_t)(n0 + i) * D_MODEL + k0 + tx] = __float2half_rn(t[tx][i]);
}

// qw,vw [16][256] fp32 -> g_qvh [32][256] fp16
__global__ void k_prep_qv(const float* __restrict__ qw, const float* __restrict__ vw){
    int i = blockIdx.x * 256 + threadIdx.x;
    if (i < 4096)      g_qvh[i] = __float2half_rn(qw[i]);
    else if (i < 8192) g_qvh[i] = __float2half_rn(vw[i - 4096]);
}

// ---------------- fused MLP + head projection (HMMA) ----------------
#define BK          32
#define KT_TILES    (D_MODEL / BK)      // 64
#define A32_PITCH   144                 // bytes per A fp32 smem row (lane*36w -> lane*4 banks)
#define B_STRIDE    80                  // bytes per B fp16 smem row
#define A16_PITCH   80                  // bytes per A fp16 smem row
#define A32_BYTES   (128 * A32_PITCH)   // 18432
#define B_BYTES     (256 * B_STRIDE)    // 20480
#define STAGE_BYTES (A32_BYTES + B_BYTES)   // 38912
#define N_STAGES    4
#define A16_BYTES   (128 * A16_PITCH)   // 10240
#define A16_OFF     (N_STAGES * STAGE_BYTES)        // 155648
#define SMEM_DYN    (A16_OFF + 2 * A16_BYTES)       // 176128

__device__ __forceinline__ void load_stage(const float* __restrict__ x, size_t m0,
                                           int kt, uint32_t sA, uint32_t sB, int tid){
    #pragma unroll
    for (int i = 0; i < 2; i++){
        int ch  = tid + i * 512;            // 0..1023
        int row = ch >> 3, c = ch & 7;      // A: 128 rows x 8 chunks of 16B
        const float* src = x + (m0 + row) * D_MODEL + (size_t)kt * BK + c * 4;
        uint32_t dst = sA + row * A32_PITCH + c * 16;
        asm volatile("cp.async.cg.shared.global [%0], [%1], 16;" :: "r"(dst), "l"(src));
    }
    #pragma unroll
    for (int i = 0; i < 2; i++){
        int ch  = tid + i * 512;
        int row = ch >> 2, c = ch & 3;      // B: 256 rows x 4 chunks of 16B
        const char* src = (const char*)g_w1h + (size_t)row * (D_MODEL * 2) + kt * (BK * 2) + c * 16;
        uint32_t dst = sB + row * B_STRIDE + c * 16;
        asm volatile("cp.async.cg.shared.global [%0], [%1], 16;" :: "r"(dst), "l"(src));
    }
}

// CTA-cooperative fp32 -> fp16 conversion of one 128x32 A tile
__device__ __forceinline__ void convert_tile(const char* stage, char* a16, int tid){
    int row = tid & 127;
    int cg  = tid >> 7;                     // 0..3 (8-float group)
    const float4* p = (const float4*)(stage + row * A32_PITCH + cg * 32);
    float4 v0 = p[0], v1 = p[1];
    uint4 o;
    o.x = pack_h2(v0.x, v0.y); o.y = pack_h2(v0.z, v0.w);
    o.z = pack_h2(v1.x, v1.y); o.w = pack_h2(v1.z, v1.w);
    *(uint4*)(a16 + row * A16_PITCH + cg * 16) = o;
}

__global__ __launch_bounds__(512, 1)
void k_mlp(const float* __restrict__ x, const float* __restrict__ b1)
{
    extern __shared__ __align__(16) char dyn[];
    __shared__ unsigned smax[N_HEADS];

    const int tid  = threadIdx.x;
    const int wid  = tid >> 5;
    const int lane = tid & 31;
    const int mw   = wid >> 2;      // 0..3  M warp
    const int nw   = wid & 3;       // 0..3  N warp
    const int rq   = lane >> 2;     // 0..7
    const int cq   = (lane & 3) * 2;
    const int m_   = lane >> 3;     // ldmatrix matrix id
    const int r_   = lane & 7;      // ldmatrix row
    const size_t m0 = (size_t)blockIdx.x * 128;

    const uint32_t dbase = smem_u32(dyn);
    if (tid < N_HEADS) smax[tid] = ~0xFF800000u;

    float acc[2][8][4];
    #pragma unroll
    for (int mt = 0; mt < 2; mt++)
        #pragma unroll
        for (int nt = 0; nt < 8; nt++)
            #pragma unroll
            for (int k = 0; k < 4; k++) acc[mt][nt][k] = 0.f;

    // prologue: 3 stages in flight, convert tile 0
    #pragma unroll
    for (int p = 0; p < 3; p++){
        uint32_t st = dbase + p * STAGE_BYTES;
        load_stage(x, m0, p, st, st + A32_BYTES, tid);
        asm volatile("cp.async.commit_group;" ::: "memory");
    }
    asm volatile("cp.async.wait_group 2;" ::: "memory");
    __syncthreads();
    convert_tile(dyn, dyn + A16_OFF, tid);

    for (int kt = 0; kt < KT_TILES; kt++){
        asm volatile("cp.async.wait_group 1;" ::: "memory");
        __syncthreads();   // publishes: stage kt+1 data, A16[kt&1] writes, frees A16[(kt+1)&1]

        if (kt + 1 < KT_TILES)
            convert_tile(dyn + ((kt + 1) % N_STAGES) * STAGE_BYTES,
                         dyn + A16_OFF + ((kt + 1) & 1) * A16_BYTES, tid);

        if (kt + 3 < KT_TILES){
            uint32_t ns = dbase + ((kt + 3) % N_STAGES) * STAGE_BYTES;
            load_stage(x, m0, kt + 3, ns, ns + A32_BYTES, tid);
        }
        asm volatile("cp.async.commit_group;" ::: "memory");

        const uint32_t sB  = dbase + (kt % N_STAGES) * STAGE_BYTES + A32_BYTES;
        const uint32_t sAh = dbase + A16_OFF + (kt & 1) * A16_BYTES;

        #pragma unroll
        for (int ks = 0; ks < 2; ks++){
            uint32_t bf[8][2];
            #pragma unroll
            for (int ng = 0; ng < 4; ng++){
                int nrow = nw * 64 + ng * 16 + ((m_ >> 1) * 8) + r_;
                uint32_t addr = sB + nrow * B_STRIDE + (ks * 16 + (m_ & 1) * 8) * 2;
                LDMX4(bf[ng*2][0], bf[ng*2][1], bf[ng*2+1][0], bf[ng*2+1][1], addr);
            }
            uint32_t af[2][4];
            #pragma unroll
            for (int mt = 0; mt < 2; mt++){
                int arow = mw * 32 + mt * 16 + (m_ & 1) * 8 + r_;
                uint32_t aaddr = sAh + arow * A16_PITCH + (ks * 16 + (m_ >> 1) * 8) * 2;
                LDMX4(af[mt][0], af[mt][1], af[mt][2], af[mt][3], aaddr);
            }
            #pragma unroll
            for (int mt = 0; mt < 2; mt++)
                #pragma unroll
                for (int nt = 0; nt < 8; nt++)
                    mma16816(acc[mt][nt], af[mt], bf[nt]);
        }
    }
    asm volatile("cp.async.wait_group 0;" ::: "memory");
    __syncthreads();   // mainloop smem reads done; reuse dyn below

    // ---------------- epilogue: bias + relu, then projection MMA ----------------
    #pragma unroll
    for (int nt = 0; nt < 8; nt++){
        int C = nw * 64 + nt * 8 + cq;
        float bv0 = __ldg(b1 + C), bv1 = __ldg(b1 + C + 1);
        #pragma unroll
        for (int mt = 0; mt < 2; mt++){
            acc[mt][nt][0] = fmaxf(acc[mt][nt][0] + bv0, 0.f);
            acc[mt][nt][1] = fmaxf(acc[mt][nt][1] + bv1, 0.f);
            acc[mt][nt][2] = fmaxf(acc[mt][nt][2] + bv0, 0.f);
            acc[mt][nt][3] = fmaxf(acc[mt][nt][3] + bv1, 0.f);
        }
    }

    float*  proj = (float*)dyn;                 // [128][33] fp32
    __half* qvs  = (__half*)(dyn + 17408);      // [32 rows][264 halves]
    for (int i = tid; i < 128 * 33; i += 512) proj[i] = 0.f;
    for (int i = tid; i < 32 * 256; i += 512){
        int r = i >> 8, c = i & 255;
        qvs[r * 264 + c] = g_qvh[i];
    }
    __syncthreads();

    const uint32_t qbase = smem_u32(qvs);
    #pragma unroll
    for (int mt = 0; mt < 2; mt++){
        float cp[4][4];
        #pragma unroll
        for (int ht = 0; ht < 4; ht++)
            #pragma unroll
            for (int k = 0; k < 4; k++) cp[ht][k] = 0.f;
        #pragma unroll
        for (int j = 0; j < 4; j++){    // k16 chunks within this warp's 64 hid dims
            uint32_t bh[4][2];
            #pragma unroll
            for (int hg = 0; hg < 2; hg++){
                int hrow = hg * 16 + ((m_ >> 1) * 8) + r_;
                uint32_t addr = qbase + hrow * 528 + (nw * 64 + j * 16 + (m_ & 1) * 8) * 2;
                LDMX4(bh[hg*2][0], bh[hg*2][1], bh[hg*2+1][0], bh[hg*2+1][1], addr);
            }
            uint32_t ap[4] = {
                pack_h2(acc[mt][2*j  ][0], acc[mt][2*j  ][1]),
                pack_h2(acc[mt][2*j  ][2], acc[mt][2*j  ][3]),
                pack_h2(acc[mt][2*j+1][0], acc[mt][2*j+1][1]),
                pack_h2(acc[mt][2*j+1][2], acc[mt][2*j+1][3]) };
            #pragma unroll
            for (int ht = 0; ht < 4; ht++) mma16816(cp[ht], ap, bh[ht]);
        }
        int tok = mw * 32 + mt * 16 + rq;
        #pragma unroll
        for (int ht = 0; ht < 4; ht++){
            int hd = ht * 8 + cq;
            atomicAdd(&proj[tok * 33 + hd],           cp[ht][0]);
            atomicAdd(&proj[tok * 33 + hd + 1],       cp[ht][1]);
            atomicAdd(&proj[(tok + 8) * 33 + hd],     cp[ht][2]);
            atomicAdd(&proj[(tok + 8) * 33 + hd + 1], cp[ht][3]);
        }
    }
    __syncthreads();

    #pragma unroll
    for (int i = 0; i < 8; i++){
        int idx = tid + 512 * i;       // 0..4095
        int t = idx >> 5, h = idx & 31;
        float s = proj[t * 33 + h];
        size_t gt = m0 + t;
        if (h < N_HEADS){
            g_L[gt * N_HEADS + h] = s;
            atomicMax(&smax[h], f2ord(s));
        } else {
            g_Vv[gt * N_HEADS + (h - N_HEADS)] = s;
        }
    }
    __syncthreads();
    if (tid < N_HEADS) atomicMax(&g_logit_max[tid], smax[tid]);
}

// Sliding-window softmax-weighted mean, max over windows per head
__global__ __launch_bounds__(256)
void k_window(int n)
{
    __shared__ float    es [N_HEADS][328];
    __shared__ float    evs[N_HEADS][328];
    __shared__ float    mval[N_HEADS];
    __shared__ unsigned smax[N_HEADS];

    const int tid = threadIdx.x;
    const int w0  = blockIdx.x * 256;
    const int NW  = n - WINDOW + 1;

    if (tid < N_HEADS){
        mval[tid] = ord2f(g_logit_max[tid]);
        smax[tid] = f2ord(-INFINITY);
    }
    __syncthreads();

    int ntok = n - w0;
    if (ntok > 256 + WINDOW - 1) ntok = 256 + WINDOW - 1;
    for (int idx = tid; idx < ntok * N_HEADS; idx += 256){
        int h = idx & (N_HEADS - 1);
        int t = idx >> 4;
        size_t g = (size_t)(w0 + t) * N_HEADS + h;
        float e = expf(g_L[g] - mval[h]);
        es [h][t] = e;
        evs[h][t] = e * g_Vv[g];
    }
    __syncthreads();

    if (w0 + tid < NW){
        #pragma unroll 1
        for (int h = 0; h < N_HEADS; h++){
            float se = 0.f, sev = 0.f;
            #pragma unroll 16
            for (int j = 0; j < WINDOW; j++){
                se  += es [h][tid + j];
                sev += evs[h][tid + j];
            }
            atomicMax(&smax[h], f2ord(sev / se));
        }
    }
    __syncthreads();
    if (tid < N_HEADS) atomicMax(&g_score_max[tid], smax[tid]);
}

__global__ void k_final(float* out){
    int t = threadIdx.x;
    float s = (t < N_HEADS) ? ord2f(g_score_max[t]) : 0.f;
    #pragma unroll
    for (int off = 16; off; off >>= 1)
        s += __shfl_down_sync(0xffffffffu, s, off);
    if (t == 0) out[0] = s;
}

extern "C" void kernel_launch(void* const* d_in, const int* in_sizes, int n_in,
                              void* d_out, int out_size)
{
    const float* x  = (const float*)d_in[0];
    const float* w1 = (const float*)d_in[1];
    const float* b1 = (const float*)d_in[2];
    const float* qw = (const float*)d_in[3];
    const float* vw = (const float*)d_in[4];
    int n = in_sizes[0] / D_MODEL;

    cudaFuncSetAttribute(k_mlp, cudaFuncAttributeMaxDynamicSharedMemorySize, SMEM_DYN);

    k_init<<<1, 32>>>();
    k_prep_w<<<dim3(D_MODEL / 32, D_HID / 32), dim3(32, 8)>>>(w1);
    k_prep_qv<<<32, 256>>>(qw, vw);
    k_mlp<<<n / 128, 512, SMEM_DYN>>>(x, b1);
    int NW = n - WINDOW + 1;
    k_window<<<(NW + 255) / 256, 256>>>(n);
    k_final<<<1, 32>>>((float*)d_out);
}